// round 2
// baseline (speedup 1.0000x reference)
#include <cuda_runtime.h>

#define BB 512
#define TT 168
#define HH 512
#define GG 2048   // 4*H
#define GI 8      // batch slices
#define GJ 16     // unit slices
#define NCTA (GI*GJ)   // 128 persistent CTAs (<= 148 SMs, all resident)
#define RB 64     // batch rows per CTA
#define UN 32     // hidden units per CTA (x4 gates = 128 gate cols)
#define GC 128
#define KC 32     // K chunk
#define NTHR 256

// ---- static device scratch (no allocations allowed) ----
__device__ float g_h1[2][BB][HH];          // 2 MB double-buffered layer-1 hidden
__device__ float g_h2[2][BB][HH];          // 2 MB double-buffered layer-2 hidden
__device__ float g_partial[GJ][BB * TT];   // per-unit-slice partial fc dots
__device__ unsigned g_bar_cnt;             // returns to 0 every barrier -> replay-safe
__device__ volatile unsigned g_bar_gen;    // monotonically increasing generation

__device__ __forceinline__ float sigmoidf_(float x) {
    return 1.0f / (1.0f + __expf(-x));
}

// Sense-free generation barrier. All 128 CTAs are guaranteed co-resident
// (1 CTA/SM, 256 threads, <48KB static smem), so spinning is deadlock-free.
__device__ __forceinline__ void grid_sync_() {
    __syncthreads();
    if (threadIdx.x == 0) {
        __threadfence();                       // publish h writes
        unsigned gen = g_bar_gen;
        if (atomicAdd(&g_bar_cnt, 1u) == NCTA - 1u) {
            g_bar_cnt = 0u;
            __threadfence();
            g_bar_gen = gen + 1u;
        } else {
            while (g_bar_gen == gen) { }
            __threadfence();                   // acquire
        }
    }
    __syncthreads();
}

struct Smem {
    float As[RB][33];        // A tile, padded: conflict-free stores & broadcast reads
    float Ws[KC][GC];        // W tile, [k][q*32+u]
    float W1c[GC], b1c[GC], b2c[GC];
    float V1c[4][GC], V2c[4][GC];
    float fcwc[UN];
    float red[UN][RB + 1];   // padded 65-stride: conflict-free reduce
};

// acc[8 rows][4 gates] += A[64 x 512] * Wslice[512 x 128]
// A: row stride HH. W: row stride GG; local col (q,u) -> global col q*HH + ubase + u.
__device__ __forceinline__ void gemm_acc(const float* __restrict__ A,
                                         const float* __restrict__ W,
                                         int ubase, float acc[8][4],
                                         Smem* s, int rg, int u) {
    const int tid = threadIdx.x;
    const int rA = tid >> 2;            // 0..63
    const int kl = (tid & 3) << 3;      // 0,8,16,24
    const int cc = tid & 127;
    const int kb = tid >> 7;            // 0 or 1
    const int q  = cc >> 5;
    const int uu = cc & 31;

    for (int k0 = 0; k0 < HH; k0 += KC) {
        __syncthreads();
        // --- load A tile (coalesced float4 x2 per thread) ---
        {
            const float4* src = reinterpret_cast<const float4*>(A + (size_t)rA * HH + k0 + kl);
            float4 v0 = src[0], v1 = src[1];
            float* dst = &s->As[rA][kl];
            dst[0] = v0.x; dst[1] = v0.y; dst[2] = v0.z; dst[3] = v0.w;
            dst[4] = v1.x; dst[5] = v1.y; dst[6] = v1.z; dst[7] = v1.w;
        }
        // --- load W tile: 32k x 128c, 128B-coalesced runs ---
        {
            const float* wp = W + (size_t)(k0 + kb) * GG + q * HH + ubase + uu;
            #pragma unroll
            for (int kk = 0; kk < KC; kk += 2)
                s->Ws[kk + kb][cc] = wp[(size_t)kk * GG];
        }
        __syncthreads();
        // --- micro-kernel: 8x4 per thread ---
        #pragma unroll 4
        for (int k = 0; k < KC; k++) {
            float a[8], w[4];
            #pragma unroll
            for (int rr = 0; rr < 8; rr++) a[rr] = s->As[rg * 8 + rr][k];
            #pragma unroll
            for (int qq = 0; qq < 4; qq++) w[qq] = s->Ws[k][qq * 32 + u];
            #pragma unroll
            for (int rr = 0; rr < 8; rr++)
                #pragma unroll
                for (int qq = 0; qq < 4; qq++)
                    acc[rr][qq] = fmaf(a[rr], w[qq], acc[rr][qq]);
        }
    }
}

__global__ void __launch_bounds__(NTHR, 1)
pew_kernel(const float* __restrict__ inputs, const float* __restrict__ W1,
           const float* __restrict__ U1, const float* __restrict__ V1,
           const float* __restrict__ b1, const float* __restrict__ W2,
           const float* __restrict__ U2, const float* __restrict__ V2,
           const float* __restrict__ b2, const float* __restrict__ fc_w) {
    __shared__ Smem s;
    const int tid = threadIdx.x;
    const int bi = blockIdx.x >> 4;   // / GJ
    const int bj = blockIdx.x & 15;   // % GJ
    const int bbase = bi * RB;
    const int ubase = bj * UN;
    const int u  = tid & 31;
    const int rg = tid >> 5;

    // cache per-CTA gate-column constants
    for (int c = tid; c < GC; c += NTHR) {
        int q = c >> 5, uu = c & 31;
        int gcol = q * HH + ubase + uu;
        s.W1c[c] = W1[gcol];
        s.b1c[c] = b1[gcol];
        s.b2c[c] = b2[gcol];
        #pragma unroll
        for (int w = 0; w < 4; w++) {
            s.V1c[w][c] = V1[w * GG + gcol];
            s.V2c[w][c] = V2[w * GG + gcol];
        }
    }
    if (tid < UN) s.fcwc[tid] = fc_w[ubase + tid];
    __syncthreads();

    float c1[8], c2[8];
    #pragma unroll
    for (int rr = 0; rr < 8; rr++) { c1[rr] = 0.f; c2[rr] = 0.f; }

    for (int t = 0; t < TT; t++) {
        const int cur = t & 1, prev = cur ^ 1;

        // ================= layer 1 =================
        float acc[8][4];
        #pragma unroll
        for (int rr = 0; rr < 8; rr++)
            #pragma unroll
            for (int q = 0; q < 4; q++) acc[rr][q] = 0.f;

        if (t > 0) gemm_acc(&g_h1[prev][bbase][0], U1, ubase, acc, &s, rg, u);

        #pragma unroll
        for (int rr = 0; rr < 8; rr++) {
            int b_ = bbase + rg * 8 + rr;
            const float* inp = inputs + ((size_t)b_ * TT + t) * 5;
            float w0 = inp[0], w1 = inp[1], w2 = inp[2], w3 = inp[3], x = inp[4];
            #pragma unroll
            for (int q = 0; q < 4; q++) {
                int c = q * 32 + u;
                float p = s.b1c[c];
                p = fmaf(x,  s.W1c[c],    p);
                p = fmaf(w0, s.V1c[0][c], p);
                p = fmaf(w1, s.V1c[1][c], p);
                p = fmaf(w2, s.V1c[2][c], p);
                p = fmaf(w3, s.V1c[3][c], p);
                acc[rr][q] += p;
            }
            float ig = sigmoidf_(acc[rr][0]);
            float fg = sigmoidf_(acc[rr][1]);
            float gv = tanhf(acc[rr][2]);
            float og = sigmoidf_(acc[rr][3]);
            c1[rr] = fmaf(fg, c1[rr], ig * gv);
            g_h1[cur][b_][ubase + u] = og * tanhf(c1[rr]);
        }

        grid_sync_();   // publish h1_t; also covers h2_{t-1} from previous iter

        // ================= layer 2 =================
        #pragma unroll
        for (int rr = 0; rr < 8; rr++)
            #pragma unroll
            for (int q = 0; q < 4; q++) acc[rr][q] = 0.f;

        gemm_acc(&g_h1[cur][bbase][0], W2, ubase, acc, &s, rg, u);
        if (t > 0) gemm_acc(&g_h2[prev][bbase][0], U2, ubase, acc, &s, rg, u);

        #pragma unroll
        for (int rr = 0; rr < 8; rr++) {
            int b_ = bbase + rg * 8 + rr;
            const float* inp = inputs + ((size_t)b_ * TT + t) * 5;
            float w0 = inp[0], w1 = inp[1], w2 = inp[2], w3 = inp[3];
            #pragma unroll
            for (int q = 0; q < 4; q++) {
                int c = q * 32 + u;
                float p = s.b2c[c];
                p = fmaf(w0, s.V2c[0][c], p);
                p = fmaf(w1, s.V2c[1][c], p);
                p = fmaf(w2, s.V2c[2][c], p);
                p = fmaf(w3, s.V2c[3][c], p);
                acc[rr][q] += p;
            }
            float ig = sigmoidf_(acc[rr][0]);
            float fg = sigmoidf_(acc[rr][1]);
            float gv = tanhf(acc[rr][2]);
            float og = sigmoidf_(acc[rr][3]);
            c2[rr] = fmaf(fg, c2[rr], ig * gv);
            float hv = og * tanhf(c2[rr]);
            g_h2[cur][b_][ubase + u] = hv;
            s.red[u][rg * 8 + rr] = hv * s.fcwc[u];
        }
        __syncthreads();
        if (tid < RB) {
            float sum = 0.f;
            #pragma unroll
            for (int uu2 = 0; uu2 < UN; uu2++) sum += s.red[uu2][tid];
            g_partial[bj][(size_t)(bbase + tid) * TT + t] = sum;
        }
        // next gemm_acc starts with __syncthreads(), protecting s reuse
    }
}

__global__ void reduce_kernel(float* __restrict__ out, const float* __restrict__ fc_b) {
    int n = blockIdx.x * blockDim.x + threadIdx.x;
    if (n < BB * TT) {
        float sv = fc_b[0];
        #pragma unroll
        for (int j = 0; j < GJ; j++) sv += g_partial[j][n];
        out[n] = sv;
    }
}

extern "C" void kernel_launch(void* const* d_in, const int* in_sizes, int n_in,
                              void* d_out, int out_size) {
    const float* inputs = (const float*)d_in[0];
    const float* W1  = (const float*)d_in[1];
    const float* U1  = (const float*)d_in[2];
    const float* V1  = (const float*)d_in[3];
    const float* b1  = (const float*)d_in[4];
    const float* W2  = (const float*)d_in[5];
    const float* U2  = (const float*)d_in[6];
    const float* V2  = (const float*)d_in[7];
    const float* b2  = (const float*)d_in[8];
    const float* fcw = (const float*)d_in[9];
    const float* fcb = (const float*)d_in[10];

    pew_kernel<<<NCTA, NTHR>>>(inputs, W1, U1, V1, b1, W2, U2, V2, b2, fcw);
    reduce_kernel<<<(BB * TT + 255) / 256, 256>>>((float*)d_out, fcb);
}

// round 15
// speedup vs baseline: 3.1519x; 3.1519x over previous
#include <cuda_runtime.h>
#include <cuda_bf16.h>
#include <cstdint>

#define BB 512
#define TT 168
#define HH 512
#define GG 2048
#define GI 4
#define GJ 32
#define NCTA (GI*GJ)
#define RB 128
#define UN 16
#define KC 64
#define NTHR 256

// smem layout (bytes). Buffer: Ah 16K | Al 16K | Bh 8K | Bl 8K = 48K
#define OFF_BUF0 0
#define OFF_BUF1 49152
#define OFF_SRED 98304                  // float[128][65] = 33280
#define OFF_PR   131584                 // float[16][129] = 8256
#define OFF_CONST 139840                // consts ~2.9KB
#define SMEM_TOTAL 142848

// ---------------- device scratch (separate hi/lo bf16 planes) ----------------
__device__ __nv_bfloat16 g_h1h[2][BB * HH];
__device__ __nv_bfloat16 g_h1l[2][BB * HH];
__device__ __nv_bfloat16 g_h2h[2][BB * HH];
__device__ __nv_bfloat16 g_h2l[2][BB * HH];
__device__ __nv_bfloat16 g_Wh[3][GG * HH];   // [gatecol][k]; 0:U1 1:W2 2:U2
__device__ __nv_bfloat16 g_Wl[3][GG * HH];
__device__ float g_partial[GJ][BB * TT];
__device__ unsigned g_bar_cnt;
__device__ volatile unsigned g_bar_gen;

// ---------------- helpers ----------------
__device__ __forceinline__ uint32_t smem_u32(const void* p) {
    uint32_t a;
    asm("{ .reg .u64 t; cvta.to.shared.u64 t, %1; cvt.u32.u64 %0, t; }" : "=r"(a) : "l"(p));
    return a;
}
__device__ __forceinline__ float sigmoidf_(float x) { return 1.0f / (1.0f + __expf(-x)); }

#define CP_COMMIT() asm volatile("cp.async.commit_group;" ::: "memory")
#define CP_WAIT(n)  asm volatile("cp.async.wait_group %0;" :: "n"(n) : "memory")
__device__ __forceinline__ void cpa16(uint32_t dst, const void* src) {
    asm volatile("cp.async.cg.shared.global [%0], [%1], 16;" :: "r"(dst), "l"(src));
}
#define LDM4(r, addr) asm volatile( \
    "ldmatrix.sync.aligned.m8n8.x4.shared.b16 {%0,%1,%2,%3}, [%4];" \
    : "=r"((r)[0]),"=r"((r)[1]),"=r"((r)[2]),"=r"((r)[3]) : "r"(addr))
#define MMA(d, a, b) asm volatile( \
    "mma.sync.aligned.m16n8k16.row.col.f32.bf16.bf16.f32 " \
    "{%0,%1,%2,%3},{%4,%5,%6,%7},{%8,%9},{%0,%1,%2,%3};" \
    : "+f"((d)[0]),"+f"((d)[1]),"+f"((d)[2]),"+f"((d)[3]) \
    : "r"((a)[0]),"r"((a)[1]),"r"((a)[2]),"r"((a)[3]),"r"((b)[0]),"r"((b)[1]))

__device__ __forceinline__ void grid_sync_() {
    __syncthreads();
    if (threadIdx.x == 0) {
        __threadfence();
        unsigned gen = g_bar_gen;
        if (atomicAdd(&g_bar_cnt, 1u) == NCTA - 1u) {
            g_bar_cnt = 0u;
            __threadfence();
            g_bar_gen = gen + 1u;
        } else {
            while (g_bar_gen == gen) { }
            __threadfence();
        }
    }
    __syncthreads();
}

// ---------------- weight prep: transpose + bf16 hi/lo split ----------------
__global__ void prep_kernel(const float* __restrict__ U1, const float* __restrict__ W2,
                            const float* __restrict__ U2) {
    __shared__ float tile[32][33];
    const float* src = (blockIdx.z == 0) ? U1 : (blockIdx.z == 1) ? W2 : U2;
    __nv_bfloat16* dh = g_Wh[blockIdx.z];
    __nv_bfloat16* dl = g_Wl[blockIdx.z];
    int g0 = blockIdx.x * 32, k0 = blockIdx.y * 32;
    int tx = threadIdx.x, ty = threadIdx.y;
    #pragma unroll
    for (int i = 0; i < 32; i += 8)
        tile[ty + i][tx] = src[(size_t)(k0 + ty + i) * GG + g0 + tx];
    __syncthreads();
    #pragma unroll
    for (int i = 0; i < 32; i += 8) {
        float v = tile[tx][ty + i];
        __nv_bfloat16 h = __float2bfloat16(v);
        __nv_bfloat16 l = __float2bfloat16(v - __bfloat162float(h));
        size_t o = (size_t)(g0 + ty + i) * HH + k0 + tx;
        dh[o] = h;  dl[o] = l;
    }
}

// ---------------- chunk staging via cp.async (SW128-swizzled dst) ----------------
__device__ __forceinline__ void stage_issue(uint32_t dst,
        const __nv_bfloat16* __restrict__ ah, const __nv_bfloat16* __restrict__ al, int bbase,
        const __nv_bfloat16* __restrict__ wh, const __nv_bfloat16* __restrict__ wl, int ubase,
        int k0, int tid) {
    #pragma unroll
    for (int i = 0; i < 4; i++) {               // A: 128 rows x 8 kq x 16B, hi+lo
        int idx = tid + NTHR * i;
        int row = idx >> 3, kq = idx & 7;
        uint32_t off = (uint32_t)(row << 7) + (uint32_t)(kq << 4);
        uint32_t sw = off ^ ((off >> 3) & 0x70u);
        size_t so = (size_t)(bbase + row) * HH + k0 + kq * 8;
        cpa16(dst + sw,         ah + so);
        cpa16(dst + 16384 + sw, al + so);
    }
    #pragma unroll
    for (int i = 0; i < 2; i++) {               // B: 64 gatecol-rows x 8 kq x 16B, hi+lo
        int idx = tid + NTHR * i;
        int row = idx >> 3, kq = idx & 7;
        int gcol = ((row >> 4) << 9) + ubase + (row & 15);
        uint32_t off = (uint32_t)(row << 7) + (uint32_t)(kq << 4);
        uint32_t sw = off ^ ((off >> 3) & 0x70u);
        size_t so = (size_t)gcol * HH + k0 + kq * 8;
        cpa16(dst + 32768 + sw, wh + so);
        cpa16(dst + 40960 + sw, wl + so);
    }
}

// ---------------- mma on one staged K=64 chunk ----------------
// Per-lane precomputed addressing: addr = base + q + (((ks<<5)) ^ m60)
struct LaneAddr { uint32_t qA[2], mA[2], qB[2], mB[2]; };

__device__ __forceinline__ void mma_chunk(float (&d)[2][4][4], uint32_t abase,
                                          const LaneAddr& la) {
    #pragma unroll
    for (int ks = 0; ks < 4; ks++) {
        uint32_t ahf[2][4], alf[2][4], bhf[2][4], blf[2][4];
        #pragma unroll
        for (int rb = 0; rb < 2; rb++) {
            uint32_t ad = abase + la.qA[rb] + (((uint32_t)(ks << 5)) ^ la.mA[rb]);
            LDM4(ahf[rb], ad);
            LDM4(alf[rb], ad + 16384);
        }
        #pragma unroll
        for (int pb = 0; pb < 2; pb++) {
            uint32_t bd = abase + 32768 + la.qB[pb] + (((uint32_t)(ks << 5)) ^ la.mB[pb]);
            LDM4(bhf[pb], bd);
            LDM4(blf[pb], bd + 8192);
        }
        #pragma unroll
        for (int rb = 0; rb < 2; rb++)
            #pragma unroll
            for (int nb = 0; nb < 4; nb++) {
                uint32_t* bh = &bhf[nb >> 1][(nb & 1) * 2];
                uint32_t* bl = &blf[nb >> 1][(nb & 1) * 2];
                MMA(d[rb][nb], ahf[rb], bh);
                MMA(d[rb][nb], ahf[rb], bl);
                MMA(d[rb][nb], alf[rb], bh);
            }
    }
}

// ---------------- pipelined gemm over nchunks (chunks >=8 switch source) ----------
__device__ void gemm_run(uint32_t smb, float (&d)[2][4][4],
        const __nv_bfloat16* ah1, const __nv_bfloat16* al1,
        const __nv_bfloat16* wh1, const __nv_bfloat16* wl1,
        const __nv_bfloat16* ah2, const __nv_bfloat16* al2,
        const __nv_bfloat16* wh2, const __nv_bfloat16* wl2,
        int nchunks, int bbase, int ubase, int tid, const LaneAddr& la) {
    stage_issue(smb + OFF_BUF0, ah1, al1, bbase, wh1, wl1, ubase, 0, tid);
    CP_COMMIT();
    for (int c = 0; c < nchunks; c++) {
        if (c + 1 < nchunks) {
            int cc = c + 1;
            bool s2 = cc >= 8;
            stage_issue(smb + ((cc & 1) ? OFF_BUF1 : OFF_BUF0),
                        s2 ? ah2 : ah1, s2 ? al2 : al1, bbase,
                        s2 ? wh2 : wh1, s2 ? wl2 : wl1, ubase, (cc & 7) * KC, tid);
            CP_COMMIT();
            CP_WAIT(1);
        } else {
            CP_WAIT(0);
        }
        __syncthreads();
        mma_chunk(d, smb + ((c & 1) ? OFF_BUF1 : OFF_BUF0), la);
        __syncthreads();
    }
}

// ---------------- main persistent kernel ----------------
__global__ void __launch_bounds__(NTHR, 1)
pew_kernel(const float* __restrict__ inputs, const float* __restrict__ W1,
           const float* __restrict__ V1, const float* __restrict__ b1,
           const float* __restrict__ V2, const float* __restrict__ b2,
           const float* __restrict__ fc_w) {
    extern __shared__ char sm[];
    const int tid = threadIdx.x;
    const int wid = tid >> 5, lid = tid & 31;
    const int mg = wid & 3, ng = wid >> 2;     // warp tile: rows mg*32+.., cols ng*32+..
    const int bi = blockIdx.x >> 5, bj = blockIdx.x & 31;
    const int bbase = bi * RB, ubase = bj * UN;
    const uint32_t smb = smem_u32(sm);

    float* W1c = (float*)(sm + OFF_CONST);
    float* b1c = W1c + 64;
    float* b2c = b1c + 64;
    float* V1c = b2c + 64;      // [4][64]
    float* V2c = V1c + 256;     // [4][64]
    float* fcwc = V2c + 256;    // [16]
    float* sred = (float*)(sm + OFF_SRED);   // [128][65]
    float* pr   = (float*)(sm + OFF_PR);     // [16][129]

    if (tid < 64) {
        int q = tid >> 4, un_ = tid & 15;
        int gcol = q * HH + ubase + un_;
        W1c[tid] = W1[gcol];
        b1c[tid] = b1[gcol];
        b2c[tid] = b2[gcol];
        #pragma unroll
        for (int w = 0; w < 4; w++) {
            V1c[w * 64 + tid] = V1[w * GG + gcol];
            V2c[w * 64 + tid] = V2[w * GG + gcol];
        }
    }
    if (tid < UN) fcwc[tid] = fc_w[ubase + tid];
    __syncthreads();

    // per-lane ldmatrix address precompute
    LaneAddr la;
    {
        int l = lid;
        #pragma unroll
        for (int rb = 0; rb < 2; rb++) {
            int row = mg * 32 + rb * 16 + (l & 15);
            uint32_t kb0 = (l & 16) ? 16u : 0u;
            uint32_t m = (uint32_t)(row & 7) << 4;
            la.qA[rb] = (uint32_t)(row << 7) + (kb0 ^ (m & 16u));
            la.mA[rb] = m & 0x60u;
        }
        #pragma unroll
        for (int pb = 0; pb < 2; pb++) {
            int row = ng * 32 + pb * 16 + ((l & 16) ? 8 : 0) + (l & 7);
            uint32_t kb0 = (l & 8) ? 16u : 0u;
            uint32_t m = (uint32_t)(row & 7) << 4;
            la.qB[pb] = (uint32_t)(row << 7) + (kb0 ^ (m & 16u));
            la.mB[pb] = m & 0x60u;
        }
    }

    const int un = tid & 15;
    const int rg = tid >> 4;           // 16 row groups of 8
    float c1[8], c2[8];
    #pragma unroll
    for (int rr = 0; rr < 8; rr++) { c1[rr] = 0.f; c2[rr] = 0.f; }

    float d[2][4][4];

    for (int t = 0; t < TT; t++) {
        const int cur = t & 1, prev = cur ^ 1;

        // ===== layer 1: d = h1_prev @ U1 =====
        #pragma unroll
        for (int a = 0; a < 2; a++)
            #pragma unroll
            for (int b = 0; b < 4; b++)
                #pragma unroll
                for (int c = 0; c < 4; c++) d[a][b][c] = 0.f;

        if (t > 0)
            gemm_run(smb, d, g_h1h[prev], g_h1l[prev], g_Wh[0], g_Wl[0],
                     nullptr, nullptr, nullptr, nullptr, 8, bbase, ubase, tid, la);

        // store accums to sred
        #pragma unroll
        for (int rb = 0; rb < 2; rb++)
            #pragma unroll
            for (int nb = 0; nb < 4; nb++) {
                int row0 = mg * 32 + rb * 16 + (lid >> 2);
                int col0 = ng * 32 + nb * 8 + 2 * (lid & 3);
                sred[row0 * 65 + col0]       = d[rb][nb][0];
                sred[row0 * 65 + col0 + 1]   = d[rb][nb][1];
                sred[(row0 + 8) * 65 + col0]     = d[rb][nb][2];
                sred[(row0 + 8) * 65 + col0 + 1] = d[rb][nb][3];
            }
        __syncthreads();

        #pragma unroll
        for (int rr = 0; rr < 8; rr++) {
            int row = rg * 8 + rr;
            int b_ = bbase + row;
            const float* inp = inputs + ((size_t)b_ * TT + t) * 5;
            float w0 = inp[0], w1 = inp[1], w2 = inp[2], w3 = inp[3], x = inp[4];
            float gi = sred[row * 65 + un];
            float gf = sred[row * 65 + 16 + un];
            float gg = sred[row * 65 + 32 + un];
            float go = sred[row * 65 + 48 + un];
            #define PRE1(q) (b1c[q*16+un] + x*W1c[q*16+un] + w0*V1c[0*64+q*16+un] + \
                             w1*V1c[1*64+q*16+un] + w2*V1c[2*64+q*16+un] + w3*V1c[3*64+q*16+un])
            gi += PRE1(0); gf += PRE1(1); gg += PRE1(2); go += PRE1(3);
            #undef PRE1
            float iv = sigmoidf_(gi), fv = sigmoidf_(gf), gv = tanhf(gg), ov = sigmoidf_(go);
            c1[rr] = fmaf(fv, c1[rr], iv * gv);
            float hv = ov * tanhf(c1[rr]);
            __nv_bfloat16 hh = __float2bfloat16(hv);
            __nv_bfloat16 hl = __float2bfloat16(hv - __bfloat162float(hh));
            size_t ho = (size_t)b_ * HH + ubase + un;
            g_h1h[cur][ho] = hh;
            g_h1l[cur][ho] = hl;
        }

        grid_sync_();     // publish h1_t (and h2_{t-1} from previous step)

        // ===== layer 2: d = h1_cur @ W2 + h2_prev @ U2 =====
        #pragma unroll
        for (int a = 0; a < 2; a++)
            #pragma unroll
            for (int b = 0; b < 4; b++)
                #pragma unroll
                for (int c = 0; c < 4; c++) d[a][b][c] = 0.f;

        if (t > 0)
            gemm_run(smb, d, g_h1h[cur], g_h1l[cur], g_Wh[1], g_Wl[1],
                     g_h2h[prev], g_h2l[prev], g_Wh[2], g_Wl[2],
                     16, bbase, ubase, tid, la);
        else
            gemm_run(smb, d, g_h1h[cur], g_h1l[cur], g_Wh[1], g_Wl[1],
                     nullptr, nullptr, nullptr, nullptr, 8, bbase, ubase, tid, la);

        #pragma unroll
        for (int rb = 0; rb < 2; rb++)
            #pragma unroll
            for (int nb = 0; nb < 4; nb++) {
                int row0 = mg * 32 + rb * 16 + (lid >> 2);
                int col0 = ng * 32 + nb * 8 + 2 * (lid & 3);
                sred[row0 * 65 + col0]       = d[rb][nb][0];
                sred[row0 * 65 + col0 + 1]   = d[rb][nb][1];
                sred[(row0 + 8) * 65 + col0]     = d[rb][nb][2];
                sred[(row0 + 8) * 65 + col0 + 1] = d[rb][nb][3];
            }
        __syncthreads();

        #pragma unroll
        for (int rr = 0; rr < 8; rr++) {
            int row = rg * 8 + rr;
            int b_ = bbase + row;
            const float* inp = inputs + ((size_t)b_ * TT + t) * 5;
            float w0 = inp[0], w1 = inp[1], w2 = inp[2], w3 = inp[3];
            float gi = sred[row * 65 + un];
            float gf = sred[row * 65 + 16 + un];
            float gg = sred[row * 65 + 32 + un];
            float go = sred[row * 65 + 48 + un];
            #define PRE2(q) (b2c[q*16+un] + w0*V2c[0*64+q*16+un] + w1*V2c[1*64+q*16+un] + \
                             w2*V2c[2*64+q*16+un] + w3*V2c[3*64+q*16+un])
            gi += PRE2(0); gf += PRE2(1); gg += PRE2(2); go += PRE2(3);
            #undef PRE2
            float iv = sigmoidf_(gi), fv = sigmoidf_(gf), gv = tanhf(gg), ov = sigmoidf_(go);
            c2[rr] = fmaf(fv, c2[rr], iv * gv);
            float hv = ov * tanhf(c2[rr]);
            __nv_bfloat16 hh = __float2bfloat16(hv);
            __nv_bfloat16 hl = __float2bfloat16(hv - __bfloat162float(hh));
            size_t ho = (size_t)b_ * HH + ubase + un;
            g_h2h[cur][ho] = hh;
            g_h2l[cur][ho] = hl;
            pr[un * 129 + row] = hv * fcwc[un];
        }
        __syncthreads();
        if (tid < RB) {
            float sum = 0.f;
            #pragma unroll
            for (int uu = 0; uu < UN; uu++) sum += pr[uu * 129 + tid];
            g_partial[bj][(size_t)(bbase + tid) * TT + t] = sum;
        }
        // next gemm_run's internal __syncthreads orders buffer/pr reuse
    }
}

__global__ void reduce_kernel(float* __restrict__ out, const float* __restrict__ fc_b) {
    int n = blockIdx.x * blockDim.x + threadIdx.x;
    if (n < BB * TT) {
        float sv = fc_b[0];
        #pragma unroll
        for (int j = 0; j < GJ; j++) sv += g_partial[j][n];
        out[n] = sv;
    }
}

extern "C" void kernel_launch(void* const* d_in, const int* in_sizes, int n_in,
                              void* d_out, int out_size) {
    const float* inputs = (const float*)d_in[0];
    const float* W1  = (const float*)d_in[1];
    const float* U1  = (const float*)d_in[2];
    const float* V1  = (const float*)d_in[3];
    const float* b1  = (const float*)d_in[4];
    const float* W2  = (const float*)d_in[5];
    const float* U2  = (const float*)d_in[6];
    const float* V2  = (const float*)d_in[7];
    const float* b2  = (const float*)d_in[8];
    const float* fcw = (const float*)d_in[9];
    const float* fcb = (const float*)d_in[10];

    cudaFuncSetAttribute(pew_kernel, cudaFuncAttributeMaxDynamicSharedMemorySize, SMEM_TOTAL);

    prep_kernel<<<dim3(GG / 32, HH / 32, 3), dim3(32, 8)>>>(U1, W2, U2);
    pew_kernel<<<NCTA, NTHR, SMEM_TOTAL>>>(inputs, W1, V1, b1, V2, b2, fcw);
    reduce_kernel<<<(BB * TT + 255) / 256, 256>>>((float*)d_out, fcb);
}